// round 15
// baseline (speedup 1.0000x reference)
#include <cuda_runtime.h>

#define NPTS 8192
#define BATCH 2
#define KK 20
#define FULLMASK 0xffffffffu

// -------- device scratch (no allocations allowed) --------
__device__ float g_xx[BATCH * NPTS];
__device__ int   g_idx[BATCH * NPTS * KK];
__device__ float g_pre[BATCH * NPTS * 64];   // per-point neighbor term (per layer)
__device__ float g_ctr[BATCH * NPTS * 64];   // per-point center term (per layer)
__device__ float g_cat[BATCH * NPTS * 192];  // point-major concat of x1|x2|x3

__device__ __forceinline__ float leaky(float v) { return fmaxf(v, 0.2f * v); }

__device__ __forceinline__ unsigned f2s(float f) {
    unsigned u = __float_as_uint(f);
    return u ^ (unsigned)(((int)u >> 31) | 0x80000000);
}
__device__ __forceinline__ float s2f(unsigned u) {
    unsigned x = u ^ (unsigned)(((int)(~u) >> 31) | 0x80000000);
    return __uint_as_float(x);
}

// -------- squared norms of xyz --------
__global__ void xx_kernel(const float* __restrict__ x) {
    int id = blockIdx.x * 256 + threadIdx.x;  // 0..16383
    int b = id >> 13, j = id & (NPTS - 1);
    const float* xb = x + b * 6 * NPTS;
    float a = xb[j], c = xb[NPTS + j], e = xb[2 * NPTS + j];
    g_xx[id] = a * a + c * c + e * e;
}

// -------- KNN: 2 queries/warp, replace-min top-20 (REDUX push, no cj shuffle) --------
__global__ __launch_bounds__(256) void knn_kernel(const float* __restrict__ x) {
    __shared__ float4 tile[2048];
    const int b = blockIdx.y;
    const int warp = threadIdx.x >> 5;
    const int lane = threadIdx.x & 31;
    const int qbase = blockIdx.x * 16 + warp * 2;   // 2 queries per warp
    const float* xb = x + b * 6 * NPTS;
    const float* xxb = g_xx + b * NPTS;

    float qx[2], qy[2], qz[2];
#pragma unroll
    for (int q = 0; q < 2; ++q) {
        int n = qbase + q;
        qx[q] = xb[n]; qy[q] = xb[NPTS + n]; qz[q] = xb[2 * NPTS + n];
    }

    unsigned kuv[2];
    int kj[2];
    float mnv[2];
    int mnl[2];

    // ---- prefill slots with candidates j = 0..19 ----
    {
        float cx = 0.f, cy = 0.f, cz = 0.f, cw = 0.f;
        if (lane < KK) {
            cx = xb[lane]; cy = xb[NPTS + lane]; cz = xb[2 * NPTS + lane];
            cw = xxb[lane];
        }
#pragma unroll
        for (int q = 0; q < 2; ++q) {
            float dot = fmaf(qx[q], cx, fmaf(qy[q], cy, qz[q] * cz));
            float e = fmaf(-0.5f, cw, dot);
            kuv[q] = (lane < KK) ? f2s(e) : 0xFFFFFFFFu;
            kj[q] = lane;
            unsigned mn = __reduce_min_sync(FULLMASK, kuv[q]);
            unsigned bal = __ballot_sync(FULLMASK, kuv[q] == mn);
            mnl[q] = __ffs(bal) - 1;
            mnv[q] = s2f(mn);
        }
    }

    // ---- process candidates j = 20..31 (lanes 20..31 carry them; cj == src) ----
    {
        int j = lane;
        float cx = xb[j], cy = xb[NPTS + j], cz = xb[2 * NPTS + j], cw = xxb[j];
        bool valid = (lane >= KK);
#pragma unroll
        for (int q = 0; q < 2; ++q) {
            float dot = fmaf(qx[q], cx, fmaf(qy[q], cy, qz[q] * cz));
            float e = fmaf(-0.5f, cw, dot);
            unsigned mask = __ballot_sync(FULLMASK, valid && (e > mnv[q]));
            while (mask) {
                int src = __ffs(mask) - 1; mask &= mask - 1;
                float ce = __shfl_sync(FULLMASK, e, src);
                if (ce > mnv[q]) {
                    if (lane == mnl[q]) { kuv[q] = f2s(ce); kj[q] = src; }
                    unsigned mn = __reduce_min_sync(FULLMASK, kuv[q]);
                    unsigned bal = __ballot_sync(FULLMASK, kuv[q] == mn);
                    mnl[q] = __ffs(bal) - 1;
                    mnv[q] = s2f(mn);
                }
            }
        }
    }

    // ---- main streaming loop over smem tiles ----
    for (int t = 0; t < NPTS; t += 2048) {
        __syncthreads();
        for (int i = threadIdx.x; i < 2048; i += 256) {
            int j = t + i;
            tile[i] = make_float4(xb[j], xb[NPTS + j], xb[2 * NPTS + j], xxb[j]);
        }
        __syncthreads();
        int istart = (t == 0) ? (32 + lane) : lane;
        for (int i = istart; i < 2048; i += 32) {
            float4 c = tile[i];
            int j = t + i;
            int gb = j - lane;                 // uniform group base: cj = gb + src
            float ed[2];
            float hw = -0.5f * c.w;
#pragma unroll
            for (int q = 0; q < 2; ++q) {
                float dot = fmaf(qx[q], c.x, fmaf(qy[q], c.y, qz[q] * c.z));
                ed[q] = dot + hw;
            }
            bool pr0 = ed[0] > mnv[0], pr1 = ed[1] > mnv[1];
            if (__any_sync(FULLMASK, pr0 | pr1)) {
                bool prq[2] = {pr0, pr1};
#pragma unroll
                for (int q = 0; q < 2; ++q) {
                    unsigned mask = __ballot_sync(FULLMASK, prq[q]);
                    while (mask) {
                        int src = __ffs(mask) - 1; mask &= mask - 1;
                        float ce = __shfl_sync(FULLMASK, ed[q], src);
                        if (ce > mnv[q]) {
                            if (lane == mnl[q]) { kuv[q] = f2s(ce); kj[q] = gb + src; }
                            unsigned mn = __reduce_min_sync(FULLMASK, kuv[q]);
                            unsigned bal = __ballot_sync(FULLMASK, kuv[q] == mn);
                            mnl[q] = __ffs(bal) - 1;
                            mnv[q] = s2f(mn);
                        }
                    }
                }
            }
        }
    }

#pragma unroll
    for (int q = 0; q < 2; ++q)
        if (lane < KK) g_idx[(b * NPTS + qbase + q) * KK + lane] = kj[q];
}

// -------- conv1 pre --------
__global__ __launch_bounds__(256) void pre1_kernel(const float* __restrict__ x,
                                                   const float* __restrict__ W1) {
    __shared__ float sW[384];
    for (int t = threadIdx.x; t < 384; t += 256)
        sW[t] = W1[t] * (((t % 6) < 3) ? 10.0f : 1.0f);
    __syncthreads();
    int o = threadIdx.x & 63;
    int pid = blockIdx.x * 4 + (threadIdx.x >> 6);
    int b = pid >> 13, j = pid & (NPTS - 1);
    const float* xb = x + b * 6 * NPTS;
    float acc = 0.f;
#pragma unroll
    for (int c = 0; c < 6; ++c) acc = fmaf(sW[o * 6 + c], xb[c * NPTS + j], acc);
    g_pre[pid * 64 + o] = acc;
}

// -------- conv1 gather-max (lane-held idx + shfl distribution) --------
__global__ __launch_bounds__(256) void conv1_kernel(const float* __restrict__ x,
                                                    const float* __restrict__ W1,
                                                    const float* __restrict__ b1) {
    int b = blockIdx.y;
    int lane = threadIdx.x & 31;
    int n = blockIdx.x * 8 + (threadIdx.x >> 5);
    int pid = b * NPTS + n;
    int jk = 0; float mx = 0.f, my = 0.f, mz = 0.f;
    if (lane < KK) {
        jk = g_idx[pid * KK + lane];
        const float* xb = x + b * 6 * NPTS;
        mx = xb[jk]; my = xb[NPTS + jk]; mz = xb[2 * NPTS + jk];
    }
#pragma unroll
    for (int off = 16; off; off >>= 1) {
        mx += __shfl_xor_sync(FULLMASK, mx, off);
        my += __shfl_xor_sync(FULLMASK, my, off);
        mz += __shfl_xor_sync(FULLMASK, mz, off);
    }
    float m0 = mx / (float)KK, m1 = my / (float)KK, m2 = mz / (float)KK;
    int o0 = lane, o1 = lane + 32;
    float c0 = b1[o0] - 10.0f * (W1[o0 * 6] * m0 + W1[o0 * 6 + 1] * m1 + W1[o0 * 6 + 2] * m2);
    float c1 = b1[o1] - 10.0f * (W1[o1 * 6] * m0 + W1[o1 * 6 + 1] * m1 + W1[o1 * 6 + 2] * m2);
    float v0 = -1e30f, v1 = -1e30f;
    const float* pb = g_pre + b * NPTS * 64;
#pragma unroll
    for (int k = 0; k < KK; ++k) {
        int j = __shfl_sync(FULLMASK, jk, k);
        const float* p = pb + j * 64 + lane;
        v0 = fmaxf(v0, p[0]);
        v1 = fmaxf(v1, p[32]);
    }
    float* cp = g_cat + pid * 192;
    cp[o0] = leaky(v0 + c0);
    cp[o1] = leaky(v1 + c1);
}

// -------- conv2/3 pre: vectorized (float4 weights + broadcast float4 x), 16 pts/block --------
// Accumulation in ascending-c order (nested fmaf) == scalar loop order -> bitwise-identical.
__global__ __launch_bounds__(256) void preC_kernel(const float* __restrict__ W,
                                                   const float* __restrict__ bias,
                                                   int in_off) {
    __shared__ float sWa[64][68];   // pad 68: float4-aligned rows, staggered banks
    __shared__ float sWd[64][68];
    __shared__ float sX[16][64];
    for (int t = threadIdx.x; t < 4096; t += 256) {
        int oo = t >> 6, cc = t & 63;
        float wa = W[oo * 128 + cc];
        sWa[oo][cc] = wa;
        sWd[oo][cc] = W[oo * 128 + 64 + cc] - wa;
    }
    int p0 = blockIdx.x * 16;
    for (int t = threadIdx.x; t < 1024; t += 256) {
        int pp = t >> 6, cc = t & 63;
        sX[pp][cc] = g_cat[(p0 + pp) * 192 + in_off + cc];
    }
    __syncthreads();
    int o = threadIdx.x & 63, pg = threadIdx.x >> 6;   // pg in 0..3
    float aA[4], aD[4];
#pragma unroll
    for (int i = 0; i < 4; ++i) { aA[i] = 0.f; aD[i] = 0.f; }
    for (int c0 = 0; c0 < 64; c0 += 4) {
        float4 wa4 = *(const float4*)&sWa[o][c0];
        float4 wd4 = *(const float4*)&sWd[o][c0];
#pragma unroll
        for (int i = 0; i < 4; ++i) {
            float4 xv = *(const float4*)&sX[pg + 4 * i][c0];
            aA[i] = fmaf(wa4.w, xv.w, fmaf(wa4.z, xv.z, fmaf(wa4.y, xv.y, fmaf(wa4.x, xv.x, aA[i]))));
            aD[i] = fmaf(wd4.w, xv.w, fmaf(wd4.z, xv.z, fmaf(wd4.y, xv.y, fmaf(wd4.x, xv.x, aD[i]))));
        }
    }
    float bo = bias[o];
#pragma unroll
    for (int i = 0; i < 4; ++i) {
        int pid = p0 + pg + 4 * i;
        g_pre[pid * 64 + o] = aA[i];
        g_ctr[pid * 64 + o] = aD[i] + bo;
    }
}

// -------- conv2/3 gather-max --------
__global__ __launch_bounds__(256) void convG_kernel(int out_off) {
    int b = blockIdx.y;
    int lane = threadIdx.x & 31;
    int n = blockIdx.x * 8 + (threadIdx.x >> 5);
    int pid = b * NPTS + n;
    int jk = (lane < KK) ? g_idx[pid * KK + lane] : 0;
    float z0 = g_ctr[pid * 64 + lane];
    float z1 = g_ctr[pid * 64 + 32 + lane];
    float v0 = -1e30f, v1 = -1e30f;
    const float* pb = g_pre + b * NPTS * 64;
#pragma unroll
    for (int k = 0; k < KK; ++k) {
        int j = __shfl_sync(FULLMASK, jk, k);
        const float* p = pb + j * 64 + lane;
        v0 = fmaxf(v0, p[0]);
        v1 = fmaxf(v1, p[32]);
    }
    float* cp = g_cat + pid * 192 + out_off;
    cp[lane] = leaky(v0 + z0);
    cp[32 + lane] = leaky(v1 + z1);
}

// -------- final GEMM: 128x128 block tile, 8x8 microtile (scalar FFMA) --------
__global__ __launch_bounds__(256) void final_kernel(const float* __restrict__ W4,
                                                    const float* __restrict__ b4,
                                                    float* __restrict__ out) {
    __shared__ float sA[16][128];
    __shared__ float sB[16][128];
    int b = blockIdx.z;
    int obase = blockIdx.y * 128;
    int nbase = blockIdx.x * 128;
    int t = threadIdx.x;
    float acc[8][8];
#pragma unroll
    for (int i = 0; i < 8; ++i)
#pragma unroll
        for (int jq = 0; jq < 8; ++jq) acc[i][jq] = 0.f;
    int o8l = (t & 15) * 8;
    int n8l = (t >> 4) * 8;
    int lrow = t >> 1;
    int lcc = (t & 1) * 8;
    for (int c0 = 0; c0 < 192; c0 += 16) {
        const float* wsrc = W4 + (obase + lrow) * 192 + c0 + lcc;
        float4 w0 = *(const float4*)wsrc;
        float4 w1 = *(const float4*)(wsrc + 4);
        sA[lcc + 0][lrow] = w0.x; sA[lcc + 1][lrow] = w0.y;
        sA[lcc + 2][lrow] = w0.z; sA[lcc + 3][lrow] = w0.w;
        sA[lcc + 4][lrow] = w1.x; sA[lcc + 5][lrow] = w1.y;
        sA[lcc + 6][lrow] = w1.z; sA[lcc + 7][lrow] = w1.w;
        const float* csrc = g_cat + (long)(b * NPTS + nbase + lrow) * 192 + c0 + lcc;
        float4 c0v = *(const float4*)csrc;
        float4 c1v = *(const float4*)(csrc + 4);
        sB[lcc + 0][lrow] = c0v.x; sB[lcc + 1][lrow] = c0v.y;
        sB[lcc + 2][lrow] = c0v.z; sB[lcc + 3][lrow] = c0v.w;
        sB[lcc + 4][lrow] = c1v.x; sB[lcc + 5][lrow] = c1v.y;
        sB[lcc + 6][lrow] = c1v.z; sB[lcc + 7][lrow] = c1v.w;
        __syncthreads();
#pragma unroll
        for (int c = 0; c < 16; ++c) {
            float a[8], bb[8];
#pragma unroll
            for (int i = 0; i < 8; ++i) a[i] = sA[c][o8l + i];
#pragma unroll
            for (int jq = 0; jq < 8; ++jq) bb[jq] = sB[c][n8l + jq];
#pragma unroll
            for (int i = 0; i < 8; ++i)
#pragma unroll
                for (int jq = 0; jq < 8; ++jq)
                    acc[i][jq] = fmaf(a[i], bb[jq], acc[i][jq]);
        }
        __syncthreads();
    }
    int o8 = obase + o8l, n8 = nbase + n8l;
#pragma unroll
    for (int i = 0; i < 8; ++i) {
        float bo = b4[o8 + i];
        float4 v0, v1;
        v0.x = leaky(acc[i][0] + bo); v0.y = leaky(acc[i][1] + bo);
        v0.z = leaky(acc[i][2] + bo); v0.w = leaky(acc[i][3] + bo);
        v1.x = leaky(acc[i][4] + bo); v1.y = leaky(acc[i][5] + bo);
        v1.z = leaky(acc[i][6] + bo); v1.w = leaky(acc[i][7] + bo);
        float* dst = out + ((long)(b * 256 + o8 + i)) * NPTS + n8;
        *(float4*)dst = v0;
        *(float4*)(dst + 4) = v1;
    }
}

extern "C" void kernel_launch(void* const* d_in, const int* in_sizes, int n_in,
                              void* d_out, int out_size) {
    const float* x  = (const float*)d_in[0];
    const float* W1 = (const float*)d_in[1];
    const float* b1 = (const float*)d_in[2];
    const float* W2 = (const float*)d_in[3];
    const float* b2 = (const float*)d_in[4];
    const float* W3 = (const float*)d_in[5];
    const float* b3 = (const float*)d_in[6];
    const float* W4 = (const float*)d_in[7];
    const float* b4 = (const float*)d_in[8];
    float* out = (float*)d_out;

    xx_kernel<<<64, 256>>>(x);
    knn_kernel<<<dim3(512, 2), 256>>>(x);
    pre1_kernel<<<4096, 256>>>(x, W1);
    conv1_kernel<<<dim3(1024, 2), 256>>>(x, W1, b1);
    preC_kernel<<<1024, 256>>>(W2, b2, 0);
    convG_kernel<<<dim3(1024, 2), 256>>>(64);
    preC_kernel<<<1024, 256>>>(W3, b3, 64);
    convG_kernel<<<dim3(1024, 2), 256>>>(128);
    final_kernel<<<dim3(64, 2, 2), 256>>>(W4, b4, out);
}

// round 16
// speedup vs baseline: 1.0230x; 1.0230x over previous
#include <cuda_runtime.h>

#define NPTS 8192
#define BATCH 2
#define KK 20
#define FULLMASK 0xffffffffu

// -------- device scratch (no allocations allowed) --------
__device__ float g_xx[BATCH * NPTS];
__device__ int   g_idx[BATCH * NPTS * KK];
__device__ float g_pre[BATCH * NPTS * 64];   // per-point neighbor term (per layer)
__device__ float g_ctr[BATCH * NPTS * 64];   // per-point center term (per layer)
__device__ float g_cat[BATCH * NPTS * 192];  // point-major concat of x1|x2|x3

__device__ __forceinline__ float leaky(float v) { return fmaxf(v, 0.2f * v); }

__device__ __forceinline__ unsigned f2s(float f) {
    unsigned u = __float_as_uint(f);
    return u ^ (unsigned)(((int)u >> 31) | 0x80000000);
}
__device__ __forceinline__ float s2f(unsigned u) {
    unsigned x = u ^ (unsigned)(((int)(~u) >> 31) | 0x80000000);
    return __uint_as_float(x);
}

// -------- squared norms of xyz --------
__global__ void xx_kernel(const float* __restrict__ x) {
    int id = blockIdx.x * 256 + threadIdx.x;  // 0..16383
    int b = id >> 13, j = id & (NPTS - 1);
    const float* xb = x + b * 6 * NPTS;
    float a = xb[j], c = xb[NPTS + j], e = xb[2 * NPTS + j];
    g_xx[id] = a * a + c * c + e * e;
}

// -------- KNN: 2 queries/warp, replace-min top-20 (REDUX push, no cj shuffle) --------
__global__ __launch_bounds__(256) void knn_kernel(const float* __restrict__ x) {
    __shared__ float4 tile[2048];
    const int b = blockIdx.y;
    const int warp = threadIdx.x >> 5;
    const int lane = threadIdx.x & 31;
    const int qbase = blockIdx.x * 16 + warp * 2;   // 2 queries per warp
    const float* xb = x + b * 6 * NPTS;
    const float* xxb = g_xx + b * NPTS;

    float qx[2], qy[2], qz[2];
#pragma unroll
    for (int q = 0; q < 2; ++q) {
        int n = qbase + q;
        qx[q] = xb[n]; qy[q] = xb[NPTS + n]; qz[q] = xb[2 * NPTS + n];
    }

    unsigned kuv[2];
    int kj[2];
    float mnv[2];
    int mnl[2];

    // ---- prefill slots with candidates j = 0..19 ----
    {
        float cx = 0.f, cy = 0.f, cz = 0.f, cw = 0.f;
        if (lane < KK) {
            cx = xb[lane]; cy = xb[NPTS + lane]; cz = xb[2 * NPTS + lane];
            cw = xxb[lane];
        }
#pragma unroll
        for (int q = 0; q < 2; ++q) {
            float dot = fmaf(qx[q], cx, fmaf(qy[q], cy, qz[q] * cz));
            float e = fmaf(-0.5f, cw, dot);
            kuv[q] = (lane < KK) ? f2s(e) : 0xFFFFFFFFu;
            kj[q] = lane;
            unsigned mn = __reduce_min_sync(FULLMASK, kuv[q]);
            unsigned bal = __ballot_sync(FULLMASK, kuv[q] == mn);
            mnl[q] = __ffs(bal) - 1;
            mnv[q] = s2f(mn);
        }
    }

    // ---- process candidates j = 20..31 (lanes 20..31 carry them; cj == src) ----
    {
        int j = lane;
        float cx = xb[j], cy = xb[NPTS + j], cz = xb[2 * NPTS + j], cw = xxb[j];
        bool valid = (lane >= KK);
#pragma unroll
        for (int q = 0; q < 2; ++q) {
            float dot = fmaf(qx[q], cx, fmaf(qy[q], cy, qz[q] * cz));
            float e = fmaf(-0.5f, cw, dot);
            unsigned mask = __ballot_sync(FULLMASK, valid && (e > mnv[q]));
            while (mask) {
                int src = __ffs(mask) - 1; mask &= mask - 1;
                float ce = __shfl_sync(FULLMASK, e, src);
                if (ce > mnv[q]) {
                    if (lane == mnl[q]) { kuv[q] = f2s(ce); kj[q] = src; }
                    unsigned mn = __reduce_min_sync(FULLMASK, kuv[q]);
                    unsigned bal = __ballot_sync(FULLMASK, kuv[q] == mn);
                    mnl[q] = __ffs(bal) - 1;
                    mnv[q] = s2f(mn);
                }
            }
        }
    }

    // ---- main streaming loop over smem tiles ----
    for (int t = 0; t < NPTS; t += 2048) {
        __syncthreads();
        for (int i = threadIdx.x; i < 2048; i += 256) {
            int j = t + i;
            tile[i] = make_float4(xb[j], xb[NPTS + j], xb[2 * NPTS + j], xxb[j]);
        }
        __syncthreads();
        int istart = (t == 0) ? (32 + lane) : lane;
        for (int i = istart; i < 2048; i += 32) {
            float4 c = tile[i];
            int j = t + i;
            int gb = j - lane;                 // uniform group base: cj = gb + src
            float ed[2];
            float hw = -0.5f * c.w;
#pragma unroll
            for (int q = 0; q < 2; ++q) {
                float dot = fmaf(qx[q], c.x, fmaf(qy[q], c.y, qz[q] * c.z));
                ed[q] = dot + hw;
            }
            bool pr0 = ed[0] > mnv[0], pr1 = ed[1] > mnv[1];
            if (__any_sync(FULLMASK, pr0 | pr1)) {
                bool prq[2] = {pr0, pr1};
#pragma unroll
                for (int q = 0; q < 2; ++q) {
                    unsigned mask = __ballot_sync(FULLMASK, prq[q]);
                    while (mask) {
                        int src = __ffs(mask) - 1; mask &= mask - 1;
                        float ce = __shfl_sync(FULLMASK, ed[q], src);
                        if (ce > mnv[q]) {
                            if (lane == mnl[q]) { kuv[q] = f2s(ce); kj[q] = gb + src; }
                            unsigned mn = __reduce_min_sync(FULLMASK, kuv[q]);
                            unsigned bal = __ballot_sync(FULLMASK, kuv[q] == mn);
                            mnl[q] = __ffs(bal) - 1;
                            mnv[q] = s2f(mn);
                        }
                    }
                }
            }
        }
    }

#pragma unroll
    for (int q = 0; q < 2; ++q)
        if (lane < KK) g_idx[(b * NPTS + qbase + q) * KK + lane] = kj[q];
}

// -------- conv1 pre --------
__global__ __launch_bounds__(256) void pre1_kernel(const float* __restrict__ x,
                                                   const float* __restrict__ W1) {
    __shared__ float sW[384];
    for (int t = threadIdx.x; t < 384; t += 256)
        sW[t] = W1[t] * (((t % 6) < 3) ? 10.0f : 1.0f);
    __syncthreads();
    int o = threadIdx.x & 63;
    int pid = blockIdx.x * 4 + (threadIdx.x >> 6);
    int b = pid >> 13, j = pid & (NPTS - 1);
    const float* xb = x + b * 6 * NPTS;
    float acc = 0.f;
#pragma unroll
    for (int c = 0; c < 6; ++c) acc = fmaf(sW[o * 6 + c], xb[c * NPTS + j], acc);
    g_pre[pid * 64 + o] = acc;
}

// -------- conv1 gather-max (lane-held idx + shfl distribution) --------
__global__ __launch_bounds__(256) void conv1_kernel(const float* __restrict__ x,
                                                    const float* __restrict__ W1,
                                                    const float* __restrict__ b1) {
    int b = blockIdx.y;
    int lane = threadIdx.x & 31;
    int n = blockIdx.x * 8 + (threadIdx.x >> 5);
    int pid = b * NPTS + n;
    int jk = 0; float mx = 0.f, my = 0.f, mz = 0.f;
    if (lane < KK) {
        jk = g_idx[pid * KK + lane];
        const float* xb = x + b * 6 * NPTS;
        mx = xb[jk]; my = xb[NPTS + jk]; mz = xb[2 * NPTS + jk];
    }
#pragma unroll
    for (int off = 16; off; off >>= 1) {
        mx += __shfl_xor_sync(FULLMASK, mx, off);
        my += __shfl_xor_sync(FULLMASK, my, off);
        mz += __shfl_xor_sync(FULLMASK, mz, off);
    }
    float m0 = mx / (float)KK, m1 = my / (float)KK, m2 = mz / (float)KK;
    int o0 = lane, o1 = lane + 32;
    float c0 = b1[o0] - 10.0f * (W1[o0 * 6] * m0 + W1[o0 * 6 + 1] * m1 + W1[o0 * 6 + 2] * m2);
    float c1 = b1[o1] - 10.0f * (W1[o1 * 6] * m0 + W1[o1 * 6 + 1] * m1 + W1[o1 * 6 + 2] * m2);
    float v0 = -1e30f, v1 = -1e30f;
    const float* pb = g_pre + b * NPTS * 64;
#pragma unroll
    for (int k = 0; k < KK; ++k) {
        int j = __shfl_sync(FULLMASK, jk, k);
        const float* p = pb + j * 64 + lane;
        v0 = fmaxf(v0, p[0]);
        v1 = fmaxf(v1, p[32]);
    }
    float* cp = g_cat + pid * 192;
    cp[o0] = leaky(v0 + c0);
    cp[o1] = leaky(v1 + c1);
}

// -------- conv2/3 pre: float4-vectorized, 32 pts/block (512 blocks) --------
// Weights staged c-group-major as float4: sW4[cg][o] -> warp reads consecutive o
// (conflict-free LDS.128); sX float4 reads are warp-broadcast. Accumulation in
// ascending-c order == scalar loop order -> bitwise-identical results.
__global__ __launch_bounds__(256) void preC_kernel(const float* __restrict__ W,
                                                   const float* __restrict__ bias,
                                                   int in_off) {
    __shared__ float4 sWa4[16][64];   // [c/4][o]
    __shared__ float4 sWd4[16][64];
    __shared__ float  sX[32][64];
    {
        float* wa = (float*)sWa4;
        float* wd = (float*)sWd4;
        for (int t = threadIdx.x; t < 4096; t += 256) {
            int oo = t >> 6, cc = t & 63;
            float w0 = W[oo * 128 + cc];
            int s = ((cc >> 2) * 64 + oo) * 4 + (cc & 3);
            wa[s] = w0;
            wd[s] = W[oo * 128 + 64 + cc] - w0;
        }
    }
    int p0 = blockIdx.x * 32;
    for (int t = threadIdx.x; t < 2048; t += 256) {
        int pp = t >> 6, cc = t & 63;
        sX[pp][cc] = g_cat[(p0 + pp) * 192 + in_off + cc];
    }
    __syncthreads();
    int o = threadIdx.x & 63, pg = threadIdx.x >> 6;
    float aA[8], aD[8];
#pragma unroll
    for (int i = 0; i < 8; ++i) { aA[i] = 0.f; aD[i] = 0.f; }
    for (int cg = 0; cg < 16; ++cg) {
        float4 wa4 = sWa4[cg][o];
        float4 wd4 = sWd4[cg][o];
#pragma unroll
        for (int i = 0; i < 8; ++i) {
            float4 xv = *(const float4*)&sX[pg + 4 * i][cg * 4];
            aA[i] = fmaf(wa4.w, xv.w, fmaf(wa4.z, xv.z, fmaf(wa4.y, xv.y, fmaf(wa4.x, xv.x, aA[i]))));
            aD[i] = fmaf(wd4.w, xv.w, fmaf(wd4.z, xv.z, fmaf(wd4.y, xv.y, fmaf(wd4.x, xv.x, aD[i]))));
        }
    }
    float bo = bias[o];
#pragma unroll
    for (int i = 0; i < 8; ++i) {
        int pid = p0 + pg + 4 * i;
        g_pre[pid * 64 + o] = aA[i];
        g_ctr[pid * 64 + o] = aD[i] + bo;
    }
}

// -------- conv2/3 gather-max --------
__global__ __launch_bounds__(256) void convG_kernel(int out_off) {
    int b = blockIdx.y;
    int lane = threadIdx.x & 31;
    int n = blockIdx.x * 8 + (threadIdx.x >> 5);
    int pid = b * NPTS + n;
    int jk = (lane < KK) ? g_idx[pid * KK + lane] : 0;
    float z0 = g_ctr[pid * 64 + lane];
    float z1 = g_ctr[pid * 64 + 32 + lane];
    float v0 = -1e30f, v1 = -1e30f;
    const float* pb = g_pre + b * NPTS * 64;
#pragma unroll
    for (int k = 0; k < KK; ++k) {
        int j = __shfl_sync(FULLMASK, jk, k);
        const float* p = pb + j * 64 + lane;
        v0 = fmaxf(v0, p[0]);
        v1 = fmaxf(v1, p[32]);
    }
    float* cp = g_cat + pid * 192 + out_off;
    cp[lane] = leaky(v0 + z0);
    cp[32 + lane] = leaky(v1 + z1);
}

// -------- final GEMM: 128x128 block tile, 8x8 microtile (scalar FFMA) --------
__global__ __launch_bounds__(256) void final_kernel(const float* __restrict__ W4,
                                                    const float* __restrict__ b4,
                                                    float* __restrict__ out) {
    __shared__ float sA[16][128];
    __shared__ float sB[16][128];
    int b = blockIdx.z;
    int obase = blockIdx.y * 128;
    int nbase = blockIdx.x * 128;
    int t = threadIdx.x;
    float acc[8][8];
#pragma unroll
    for (int i = 0; i < 8; ++i)
#pragma unroll
        for (int jq = 0; jq < 8; ++jq) acc[i][jq] = 0.f;
    int o8l = (t & 15) * 8;
    int n8l = (t >> 4) * 8;
    int lrow = t >> 1;
    int lcc = (t & 1) * 8;
    for (int c0 = 0; c0 < 192; c0 += 16) {
        const float* wsrc = W4 + (obase + lrow) * 192 + c0 + lcc;
        float4 w0 = *(const float4*)wsrc;
        float4 w1 = *(const float4*)(wsrc + 4);
        sA[lcc + 0][lrow] = w0.x; sA[lcc + 1][lrow] = w0.y;
        sA[lcc + 2][lrow] = w0.z; sA[lcc + 3][lrow] = w0.w;
        sA[lcc + 4][lrow] = w1.x; sA[lcc + 5][lrow] = w1.y;
        sA[lcc + 6][lrow] = w1.z; sA[lcc + 7][lrow] = w1.w;
        const float* csrc = g_cat + (long)(b * NPTS + nbase + lrow) * 192 + c0 + lcc;
        float4 c0v = *(const float4*)csrc;
        float4 c1v = *(const float4*)(csrc + 4);
        sB[lcc + 0][lrow] = c0v.x; sB[lcc + 1][lrow] = c0v.y;
        sB[lcc + 2][lrow] = c0v.z; sB[lcc + 3][lrow] = c0v.w;
        sB[lcc + 4][lrow] = c1v.x; sB[lcc + 5][lrow] = c1v.y;
        sB[lcc + 6][lrow] = c1v.z; sB[lcc + 7][lrow] = c1v.w;
        __syncthreads();
#pragma unroll
        for (int c = 0; c < 16; ++c) {
            float a[8], bb[8];
#pragma unroll
            for (int i = 0; i < 8; ++i) a[i] = sA[c][o8l + i];
#pragma unroll
            for (int jq = 0; jq < 8; ++jq) bb[jq] = sB[c][n8l + jq];
#pragma unroll
            for (int i = 0; i < 8; ++i)
#pragma unroll
                for (int jq = 0; jq < 8; ++jq)
                    acc[i][jq] = fmaf(a[i], bb[jq], acc[i][jq]);
        }
        __syncthreads();
    }
    int o8 = obase + o8l, n8 = nbase + n8l;
#pragma unroll
    for (int i = 0; i < 8; ++i) {
        float bo = b4[o8 + i];
        float4 v0, v1;
        v0.x = leaky(acc[i][0] + bo); v0.y = leaky(acc[i][1] + bo);
        v0.z = leaky(acc[i][2] + bo); v0.w = leaky(acc[i][3] + bo);
        v1.x = leaky(acc[i][4] + bo); v1.y = leaky(acc[i][5] + bo);
        v1.z = leaky(acc[i][6] + bo); v1.w = leaky(acc[i][7] + bo);
        float* dst = out + ((long)(b * 256 + o8 + i)) * NPTS + n8;
        *(float4*)dst = v0;
        *(float4*)(dst + 4) = v1;
    }
}

extern "C" void kernel_launch(void* const* d_in, const int* in_sizes, int n_in,
                              void* d_out, int out_size) {
    const float* x  = (const float*)d_in[0];
    const float* W1 = (const float*)d_in[1];
    const float* b1 = (const float*)d_in[2];
    const float* W2 = (const float*)d_in[3];
    const float* b2 = (const float*)d_in[4];
    const float* W3 = (const float*)d_in[5];
    const float* b3 = (const float*)d_in[6];
    const float* W4 = (const float*)d_in[7];
    const float* b4 = (const float*)d_in[8];
    float* out = (float*)d_out;

    xx_kernel<<<64, 256>>>(x);
    knn_kernel<<<dim3(512, 2), 256>>>(x);
    pre1_kernel<<<4096, 256>>>(x, W1);
    conv1_kernel<<<dim3(1024, 2), 256>>>(x, W1, b1);
    preC_kernel<<<512, 256>>>(W2, b2, 0);
    convG_kernel<<<dim3(1024, 2), 256>>>(64);
    preC_kernel<<<512, 256>>>(W3, b3, 64);
    convG_kernel<<<dim3(1024, 2), 256>>>(128);
    final_kernel<<<dim3(64, 2, 2), 256>>>(W4, b4, out);
}

// round 17
// speedup vs baseline: 1.0412x; 1.0178x over previous
#include <cuda_runtime.h>

#define NPTS 8192
#define BATCH 2
#define KK 20
#define FULLMASK 0xffffffffu

// -------- device scratch (no allocations allowed) --------
__device__ float g_xx[BATCH * NPTS];
__device__ int   g_idx[BATCH * NPTS * KK];
__device__ float g_pre[BATCH * NPTS * 64];   // per-point neighbor term (per layer)
__device__ float g_ctr[BATCH * NPTS * 64];   // per-point center term (per layer)
__device__ float g_cat[BATCH * NPTS * 192];  // point-major concat of x1|x2|x3

__device__ __forceinline__ float leaky(float v) { return fmaxf(v, 0.2f * v); }

__device__ __forceinline__ unsigned f2s(float f) {
    unsigned u = __float_as_uint(f);
    return u ^ (unsigned)(((int)u >> 31) | 0x80000000);
}
__device__ __forceinline__ float s2f(unsigned u) {
    unsigned x = u ^ (unsigned)(((int)(~u) >> 31) | 0x80000000);
    return __uint_as_float(x);
}

// -------- squared norms of xyz --------
__global__ void xx_kernel(const float* __restrict__ x) {
    int id = blockIdx.x * 256 + threadIdx.x;  // 0..16383
    int b = id >> 13, j = id & (NPTS - 1);
    const float* xb = x + b * 6 * NPTS;
    float a = xb[j], c = xb[NPTS + j], e = xb[2 * NPTS + j];
    g_xx[id] = a * a + c * c + e * e;
}

// -------- KNN: 2 queries/warp, replace-min top-20 (REDUX push, no cj shuffle) --------
__global__ __launch_bounds__(256) void knn_kernel(const float* __restrict__ x) {
    __shared__ float4 tile[2048];
    const int b = blockIdx.y;
    const int warp = threadIdx.x >> 5;
    const int lane = threadIdx.x & 31;
    const int qbase = blockIdx.x * 16 + warp * 2;   // 2 queries per warp
    const float* xb = x + b * 6 * NPTS;
    const float* xxb = g_xx + b * NPTS;

    float qx[2], qy[2], qz[2];
#pragma unroll
    for (int q = 0; q < 2; ++q) {
        int n = qbase + q;
        qx[q] = xb[n]; qy[q] = xb[NPTS + n]; qz[q] = xb[2 * NPTS + n];
    }

    unsigned kuv[2];
    int kj[2];
    float mnv[2];
    int mnl[2];

    // ---- prefill slots with candidates j = 0..19 ----
    {
        float cx = 0.f, cy = 0.f, cz = 0.f, cw = 0.f;
        if (lane < KK) {
            cx = xb[lane]; cy = xb[NPTS + lane]; cz = xb[2 * NPTS + lane];
            cw = xxb[lane];
        }
#pragma unroll
        for (int q = 0; q < 2; ++q) {
            float dot = fmaf(qx[q], cx, fmaf(qy[q], cy, qz[q] * cz));
            float e = fmaf(-0.5f, cw, dot);
            kuv[q] = (lane < KK) ? f2s(e) : 0xFFFFFFFFu;
            kj[q] = lane;
            unsigned mn = __reduce_min_sync(FULLMASK, kuv[q]);
            unsigned bal = __ballot_sync(FULLMASK, kuv[q] == mn);
            mnl[q] = __ffs(bal) - 1;
            mnv[q] = s2f(mn);
        }
    }

    // ---- process candidates j = 20..31 (lanes 20..31 carry them; cj == src) ----
    {
        int j = lane;
        float cx = xb[j], cy = xb[NPTS + j], cz = xb[2 * NPTS + j], cw = xxb[j];
        bool valid = (lane >= KK);
#pragma unroll
        for (int q = 0; q < 2; ++q) {
            float dot = fmaf(qx[q], cx, fmaf(qy[q], cy, qz[q] * cz));
            float e = fmaf(-0.5f, cw, dot);
            unsigned mask = __ballot_sync(FULLMASK, valid && (e > mnv[q]));
            while (mask) {
                int src = __ffs(mask) - 1; mask &= mask - 1;
                float ce = __shfl_sync(FULLMASK, e, src);
                if (ce > mnv[q]) {
                    if (lane == mnl[q]) { kuv[q] = f2s(ce); kj[q] = src; }
                    unsigned mn = __reduce_min_sync(FULLMASK, kuv[q]);
                    unsigned bal = __ballot_sync(FULLMASK, kuv[q] == mn);
                    mnl[q] = __ffs(bal) - 1;
                    mnv[q] = s2f(mn);
                }
            }
        }
    }

    // ---- main streaming loop over smem tiles ----
    for (int t = 0; t < NPTS; t += 2048) {
        __syncthreads();
        for (int i = threadIdx.x; i < 2048; i += 256) {
            int j = t + i;
            tile[i] = make_float4(xb[j], xb[NPTS + j], xb[2 * NPTS + j], xxb[j]);
        }
        __syncthreads();
        int istart = (t == 0) ? (32 + lane) : lane;
        for (int i = istart; i < 2048; i += 32) {
            float4 c = tile[i];
            int j = t + i;
            int gb = j - lane;                 // uniform group base: cj = gb + src
            float ed[2];
            float hw = -0.5f * c.w;
#pragma unroll
            for (int q = 0; q < 2; ++q) {
                float dot = fmaf(qx[q], c.x, fmaf(qy[q], c.y, qz[q] * c.z));
                ed[q] = dot + hw;
            }
            bool pr0 = ed[0] > mnv[0], pr1 = ed[1] > mnv[1];
            if (__any_sync(FULLMASK, pr0 | pr1)) {
                bool prq[2] = {pr0, pr1};
#pragma unroll
                for (int q = 0; q < 2; ++q) {
                    unsigned mask = __ballot_sync(FULLMASK, prq[q]);
                    while (mask) {
                        int src = __ffs(mask) - 1; mask &= mask - 1;
                        float ce = __shfl_sync(FULLMASK, ed[q], src);
                        if (ce > mnv[q]) {
                            if (lane == mnl[q]) { kuv[q] = f2s(ce); kj[q] = gb + src; }
                            unsigned mn = __reduce_min_sync(FULLMASK, kuv[q]);
                            unsigned bal = __ballot_sync(FULLMASK, kuv[q] == mn);
                            mnl[q] = __ffs(bal) - 1;
                            mnv[q] = s2f(mn);
                        }
                    }
                }
            }
        }
    }

#pragma unroll
    for (int q = 0; q < 2; ++q)
        if (lane < KK) g_idx[(b * NPTS + qbase + q) * KK + lane] = kj[q];
}

// -------- conv1 pre --------
__global__ __launch_bounds__(256) void pre1_kernel(const float* __restrict__ x,
                                                   const float* __restrict__ W1) {
    __shared__ float sW[384];
    for (int t = threadIdx.x; t < 384; t += 256)
        sW[t] = W1[t] * (((t % 6) < 3) ? 10.0f : 1.0f);
    __syncthreads();
    int o = threadIdx.x & 63;
    int pid = blockIdx.x * 4 + (threadIdx.x >> 6);
    int b = pid >> 13, j = pid & (NPTS - 1);
    const float* xb = x + b * 6 * NPTS;
    float acc = 0.f;
#pragma unroll
    for (int c = 0; c < 6; ++c) acc = fmaf(sW[o * 6 + c], xb[c * NPTS + j], acc);
    g_pre[pid * 64 + o] = acc;
}

// -------- conv1 gather-max (lane-held idx + shfl distribution) --------
__global__ __launch_bounds__(256) void conv1_kernel(const float* __restrict__ x,
                                                    const float* __restrict__ W1,
                                                    const float* __restrict__ b1) {
    int b = blockIdx.y;
    int lane = threadIdx.x & 31;
    int n = blockIdx.x * 8 + (threadIdx.x >> 5);
    int pid = b * NPTS + n;
    int jk = 0; float mx = 0.f, my = 0.f, mz = 0.f;
    if (lane < KK) {
        jk = g_idx[pid * KK + lane];
        const float* xb = x + b * 6 * NPTS;
        mx = xb[jk]; my = xb[NPTS + jk]; mz = xb[2 * NPTS + jk];
    }
#pragma unroll
    for (int off = 16; off; off >>= 1) {
        mx += __shfl_xor_sync(FULLMASK, mx, off);
        my += __shfl_xor_sync(FULLMASK, my, off);
        mz += __shfl_xor_sync(FULLMASK, mz, off);
    }
    float m0 = mx / (float)KK, m1 = my / (float)KK, m2 = mz / (float)KK;
    int o0 = lane, o1 = lane + 32;
    float c0 = b1[o0] - 10.0f * (W1[o0 * 6] * m0 + W1[o0 * 6 + 1] * m1 + W1[o0 * 6 + 2] * m2);
    float c1 = b1[o1] - 10.0f * (W1[o1 * 6] * m0 + W1[o1 * 6 + 1] * m1 + W1[o1 * 6 + 2] * m2);
    float v0 = -1e30f, v1 = -1e30f;
    const float* pb = g_pre + b * NPTS * 64;
#pragma unroll
    for (int k = 0; k < KK; ++k) {
        int j = __shfl_sync(FULLMASK, jk, k);
        const float* p = pb + j * 64 + lane;
        v0 = fmaxf(v0, p[0]);
        v1 = fmaxf(v1, p[32]);
    }
    float* cp = g_cat + pid * 192;
    cp[o0] = leaky(v0 + c0);
    cp[o1] = leaky(v1 + c1);
}

// -------- conv2/3 pre (scalar, proven at 232.1) --------
__global__ __launch_bounds__(256) void preC_kernel(const float* __restrict__ W,
                                                   const float* __restrict__ bias,
                                                   int in_off) {
    __shared__ float sWa[64][65];
    __shared__ float sWd[64][65];
    __shared__ float sX[32][64];
    for (int t = threadIdx.x; t < 4096; t += 256) {
        int oo = t >> 6, cc = t & 63;
        float wa = W[oo * 128 + cc];
        sWa[oo][cc] = wa;
        sWd[oo][cc] = W[oo * 128 + 64 + cc] - wa;
    }
    int p0 = blockIdx.x * 32;
    for (int t = threadIdx.x; t < 2048; t += 256) {
        int pp = t >> 6, cc = t & 63;
        sX[pp][cc] = g_cat[(p0 + pp) * 192 + in_off + cc];
    }
    __syncthreads();
    int o = threadIdx.x & 63, pg = threadIdx.x >> 6;
    float aA[8], aD[8];
#pragma unroll
    for (int i = 0; i < 8; ++i) { aA[i] = 0.f; aD[i] = 0.f; }
    for (int c = 0; c < 64; ++c) {
        float wa = sWa[o][c], wd = sWd[o][c];
#pragma unroll
        for (int i = 0; i < 8; ++i) {
            float xv = sX[pg + 4 * i][c];
            aA[i] = fmaf(wa, xv, aA[i]);
            aD[i] = fmaf(wd, xv, aD[i]);
        }
    }
    float bo = bias[o];
#pragma unroll
    for (int i = 0; i < 8; ++i) {
        int pid = p0 + pg + 4 * i;
        g_pre[pid * 64 + o] = aA[i];
        g_ctr[pid * 64 + o] = aD[i] + bo;
    }
}

// -------- conv2/3 gather-max --------
__global__ __launch_bounds__(256) void convG_kernel(int out_off) {
    int b = blockIdx.y;
    int lane = threadIdx.x & 31;
    int n = blockIdx.x * 8 + (threadIdx.x >> 5);
    int pid = b * NPTS + n;
    int jk = (lane < KK) ? g_idx[pid * KK + lane] : 0;
    float z0 = g_ctr[pid * 64 + lane];
    float z1 = g_ctr[pid * 64 + 32 + lane];
    float v0 = -1e30f, v1 = -1e30f;
    const float* pb = g_pre + b * NPTS * 64;
#pragma unroll
    for (int k = 0; k < KK; ++k) {
        int j = __shfl_sync(FULLMASK, jk, k);
        const float* p = pb + j * 64 + lane;
        v0 = fmaxf(v0, p[0]);
        v1 = fmaxf(v1, p[32]);
    }
    float* cp = g_cat + pid * 192 + out_off;
    cp[lane] = leaky(v0 + z0);
    cp[32 + lane] = leaky(v1 + z1);
}

// -------- final GEMM: 128x128 tile, 8x8 microtile, DOUBLE-BUFFERED smem --------
// Same per-element accumulation order as single-buffer version -> bitwise-identical.
__global__ __launch_bounds__(256) void final_kernel(const float* __restrict__ W4,
                                                    const float* __restrict__ b4,
                                                    float* __restrict__ out) {
    __shared__ float sA[2][16][128];
    __shared__ float sB[2][16][128];
    int b = blockIdx.z;
    int obase = blockIdx.y * 128;
    int nbase = blockIdx.x * 128;
    int t = threadIdx.x;
    float acc[8][8];
#pragma unroll
    for (int i = 0; i < 8; ++i)
#pragma unroll
        for (int jq = 0; jq < 8; ++jq) acc[i][jq] = 0.f;
    int o8l = (t & 15) * 8;
    int n8l = (t >> 4) * 8;
    int lrow = t >> 1;
    int lcc = (t & 1) * 8;

    const float* wbase = W4 + (obase + lrow) * 192 + lcc;
    const float* cbase = g_cat + (long)(b * NPTS + nbase + lrow) * 192 + lcc;

#define FINAL_LOAD(buf, c0)                                                  \
    do {                                                                     \
        const float* wsrc = wbase + (c0);                                    \
        float4 w0 = *(const float4*)wsrc;                                    \
        float4 w1 = *(const float4*)(wsrc + 4);                              \
        sA[buf][lcc + 0][lrow] = w0.x; sA[buf][lcc + 1][lrow] = w0.y;        \
        sA[buf][lcc + 2][lrow] = w0.z; sA[buf][lcc + 3][lrow] = w0.w;        \
        sA[buf][lcc + 4][lrow] = w1.x; sA[buf][lcc + 5][lrow] = w1.y;        \
        sA[buf][lcc + 6][lrow] = w1.z; sA[buf][lcc + 7][lrow] = w1.w;        \
        const float* csrc = cbase + (c0);                                    \
        float4 c0v = *(const float4*)csrc;                                   \
        float4 c1v = *(const float4*)(csrc + 4);                             \
        sB[buf][lcc + 0][lrow] = c0v.x; sB[buf][lcc + 1][lrow] = c0v.y;      \
        sB[buf][lcc + 2][lrow] = c0v.z; sB[buf][lcc + 3][lrow] = c0v.w;      \
        sB[buf][lcc + 4][lrow] = c1v.x; sB[buf][lcc + 5][lrow] = c1v.y;      \
        sB[buf][lcc + 6][lrow] = c1v.z; sB[buf][lcc + 7][lrow] = c1v.w;      \
    } while (0)

    FINAL_LOAD(0, 0);
    __syncthreads();
#pragma unroll
    for (int kb = 0; kb < 12; ++kb) {
        int cur = kb & 1;
        if (kb + 1 < 12) FINAL_LOAD(1 - cur, (kb + 1) * 16);
#pragma unroll
        for (int c = 0; c < 16; ++c) {
            float a[8], bb[8];
#pragma unroll
            for (int i = 0; i < 8; ++i) a[i] = sA[cur][c][o8l + i];
#pragma unroll
            for (int jq = 0; jq < 8; ++jq) bb[jq] = sB[cur][c][n8l + jq];
#pragma unroll
            for (int i = 0; i < 8; ++i)
#pragma unroll
                for (int jq = 0; jq < 8; ++jq)
                    acc[i][jq] = fmaf(a[i], bb[jq], acc[i][jq]);
        }
        __syncthreads();
    }
#undef FINAL_LOAD

    int o8 = obase + o8l, n8 = nbase + n8l;
#pragma unroll
    for (int i = 0; i < 8; ++i) {
        float bo = b4[o8 + i];
        float4 v0, v1;
        v0.x = leaky(acc[i][0] + bo); v0.y = leaky(acc[i][1] + bo);
        v0.z = leaky(acc[i][2] + bo); v0.w = leaky(acc[i][3] + bo);
        v1.x = leaky(acc[i][4] + bo); v1.y = leaky(acc[i][5] + bo);
        v1.z = leaky(acc[i][6] + bo); v1.w = leaky(acc[i][7] + bo);
        float* dst = out + ((long)(b * 256 + o8 + i)) * NPTS + n8;
        *(float4*)dst = v0;
        *(float4*)(dst + 4) = v1;
    }
}

extern "C" void kernel_launch(void* const* d_in, const int* in_sizes, int n_in,
                              void* d_out, int out_size) {
    const float* x  = (const float*)d_in[0];
    const float* W1 = (const float*)d_in[1];
    const float* b1 = (const float*)d_in[2];
    const float* W2 = (const float*)d_in[3];
    const float* b2 = (const float*)d_in[4];
    const float* W3 = (const float*)d_in[5];
    const float* b3 = (const float*)d_in[6];
    const float* W4 = (const float*)d_in[7];
    const float* b4 = (const float*)d_in[8];
    float* out = (float*)d_out;

    xx_kernel<<<64, 256>>>(x);
    knn_kernel<<<dim3(512, 2), 256>>>(x);
    pre1_kernel<<<4096, 256>>>(x, W1);
    conv1_kernel<<<dim3(1024, 2), 256>>>(x, W1, b1);
    preC_kernel<<<512, 256>>>(W2, b2, 0);
    convG_kernel<<<dim3(1024, 2), 256>>>(64);
    preC_kernel<<<512, 256>>>(W3, b3, 64);
    convG_kernel<<<dim3(1024, 2), 256>>>(128);
    final_kernel<<<dim3(64, 2, 2), 256>>>(W4, b4, out);
}